// round 6
// baseline (speedup 1.0000x reference)
#include <cuda_runtime.h>

// NutritionLoss: reference's Gaussian soft-lookup exp(-(id-n)^2/0.01) over
// NF=1000 foods is a numerically-exact one-hot for integer ids (off-by-one
// weight = exp(-100) ~ 3.7e-44). Collapse to a hard gather from the
// nutrition table, then per-(batch,category) signed reduction, abs, scalar sum.
//
//   loss = 5 * mean_b sum_c | sum_{d,m,s} (data[pid,c]*pamt - data[tid,c]*tamt) / 700 |
//
// R5 -> R6: removed 20KB smem staging (direct L2 gather, table is L2-hot
// across replays); single kernel via self-resetting atomicInc last-block
// reduction (kills the init-kernel graph node).

#define NF 1000
#define NC 5
#define ELEMS 448   // D*M*S = 7*4*16
#define BATCH 64
#define NWARPS 14   // 448 / 32

__device__ double d_partial[BATCH];
__device__ unsigned int d_count = 0;   // atomicInc(.,BATCH-1) wraps -> self-resets each run

__global__ __launch_bounds__(ELEMS) void nl_main(
    const float* __restrict__ y_pred,   // [B,D,M,S,2] interleaved (id, amt)
    const float* __restrict__ y,        // [B,D,M,S,2]
    const float* __restrict__ data,     // [NF,NC]
    float* __restrict__ out)            // scalar
{
    __shared__ double swarp[NWARPS][NC];
    __shared__ double scat[NC];
    __shared__ int s_last;

    const int t = threadIdx.x;
    const int b = blockIdx.x;

    // One (d,m,s) slot per thread; (id, amt) pairs interleaved -> float2.
    const float2 yp = reinterpret_cast<const float2*>(y_pred)[b * ELEMS + t];
    const float2 yt = reinterpret_cast<const float2*>(y)[b * ELEMS + t];

    const int pid = __float2int_rn(yp.x);   // matches jnp.round (no .5 cases)
    const int tid = __float2int_rn(yt.x);   // true ids are exact integers
    const double pamt = (double)yp.y;
    const double tamt = (double)yt.y;

    // Direct gather from the 20KB table (L2-resident); 10 independent LDGs.
    double acc[NC];
    #pragma unroll
    for (int c = 0; c < NC; c++)
        acc[c] = (double)__ldg(&data[pid * NC + c]) * pamt
               - (double)__ldg(&data[tid * NC + c]) * tamt;

    // Warp-level reduction of the 5 signed category sums.
    const unsigned mask = 0xffffffffu;   // 448 = 14 full warps
    #pragma unroll
    for (int c = 0; c < NC; c++) {
        double v = acc[c];
        #pragma unroll
        for (int o = 16; o > 0; o >>= 1) v += __shfl_down_sync(mask, v, o);
        if ((t & 31) == 0) swarp[t >> 5][c] = v;
    }
    __syncthreads();

    // Cross-warp reduce: thread c (c<5) sums its category over 14 warps, abs.
    if (t < NC) {
        double s = 0.0;
        #pragma unroll
        for (int w = 0; w < NWARPS; w++) s += swarp[w][t];
        scat[t] = fabs(s);
    }
    __syncthreads();

    if (t == 0) {
        d_partial[b] = scat[0] + scat[1] + scat[2] + scat[3] + scat[4];
        __threadfence();
        unsigned prev = atomicInc(&d_count, BATCH - 1);  // wraps to 0 on last block
        s_last = (prev == BATCH - 1);
    }
    __syncthreads();

    // Last block folds the 64 per-batch partials into the scalar output.
    if (s_last && t == 0) {
        double total = 0.0;
        #pragma unroll
        for (int i = 0; i < BATCH; i++) total += d_partial[i];
        // * (1/700) elementwise factor, * (1/B) batch mean, * 5 penalty
        out[0] = (float)(total * (5.0 / (700.0 * (double)BATCH)));
    }
}

extern "C" void kernel_launch(void* const* d_in, const int* in_sizes, int n_in,
                              void* d_out, int out_size) {
    const float* y_pred = (const float*)d_in[0];
    const float* y      = (const float*)d_in[1];
    const float* data   = (const float*)d_in[2];
    float* out = (float*)d_out;

    nl_main<<<BATCH, ELEMS>>>(y_pred, y, data, out);
}

// round 7
// speedup vs baseline: 1.9498x; 1.9498x over previous
#include <cuda_runtime.h>

// NutritionLoss: reference's Gaussian soft-lookup exp(-(id-n)^2/0.01) over
// NF=1000 foods is a numerically-exact one-hot for integer ids (off-by-one
// weight = exp(-100) ~ 3.7e-44). Collapse to a hard gather from the
// nutrition table, then per-(batch,category) signed reduction, abs, scalar sum.
//
//   loss = 5 * mean_b sum_c | sum_{d,m,s} (data[pid,c]*pamt - data[tid,c]*tamt) / 700 |
//
// R6 -> R7: ALL-FP32. R5/R6 were FP64-throughput-bound (~22k fp64-pipe ops
// per SM on B300's slashed fp64 pipe = the entire 12-15us). Tree summation
// keeps fp32 error ~1e-5 rel, far under the 1e-3 threshold.

#define NF 1000
#define NC 5
#define ELEMS 448   // D*M*S = 7*4*16
#define BATCH 64
#define NWARPS 14   // 448 / 32

__device__ float d_partial[BATCH];
__device__ unsigned int d_count = 0;   // atomicInc(.,BATCH-1) wraps -> self-resets each run

__global__ __launch_bounds__(ELEMS) void nl_main(
    const float* __restrict__ y_pred,   // [B,D,M,S,2] interleaved (id, amt)
    const float* __restrict__ y,        // [B,D,M,S,2]
    const float* __restrict__ data,     // [NF,NC]
    float* __restrict__ out)            // scalar
{
    __shared__ float swarp[NWARPS][NC];
    __shared__ float scat[NC];
    __shared__ int s_last;

    const int t = threadIdx.x;
    const int b = blockIdx.x;

    // One (d,m,s) slot per thread; (id, amt) pairs interleaved -> float2.
    const float2 yp = reinterpret_cast<const float2*>(y_pred)[b * ELEMS + t];
    const float2 yt = reinterpret_cast<const float2*>(y)[b * ELEMS + t];

    const int pid = __float2int_rn(yp.x);   // matches jnp.round (no .5 cases)
    const int tid = __float2int_rn(yt.x);   // true ids are exact integers
    const float pamt = yp.y;
    const float tamt = yt.y;

    // Direct gather from the 20KB table (L2-resident); 10 independent LDGs.
    float acc[NC];
    #pragma unroll
    for (int c = 0; c < NC; c++)
        acc[c] = __ldg(&data[pid * NC + c]) * pamt
               - __ldg(&data[tid * NC + c]) * tamt;

    // Warp-level tree reduction of the 5 signed category sums.
    const unsigned mask = 0xffffffffu;   // 448 = 14 full warps
    #pragma unroll
    for (int c = 0; c < NC; c++) {
        float v = acc[c];
        #pragma unroll
        for (int o = 16; o > 0; o >>= 1) v += __shfl_down_sync(mask, v, o);
        if ((t & 31) == 0) swarp[t >> 5][c] = v;
    }
    __syncthreads();

    // Cross-warp reduce: thread c (c<5) sums its category over 14 warps, abs.
    if (t < NC) {
        float s = 0.0f;
        #pragma unroll
        for (int w = 0; w < NWARPS; w++) s += swarp[w][t];
        scat[t] = fabsf(s);
    }
    __syncthreads();

    if (t == 0) {
        d_partial[b] = scat[0] + scat[1] + scat[2] + scat[3] + scat[4];
        __threadfence();
        unsigned prev = atomicInc(&d_count, BATCH - 1);  // wraps to 0 on last block
        s_last = (prev == BATCH - 1);
    }
    __syncthreads();

    // Last block folds the 64 per-batch partials into the scalar output.
    if (s_last && t == 0) {
        float total = 0.0f;
        #pragma unroll
        for (int i = 0; i < BATCH; i++) total += d_partial[i];
        // * (1/700) elementwise factor, * (1/B) batch mean, * 5 penalty
        out[0] = total * (5.0f / (700.0f * (float)BATCH));
    }
}

extern "C" void kernel_launch(void* const* d_in, const int* in_sizes, int n_in,
                              void* d_out, int out_size) {
    const float* y_pred = (const float*)d_in[0];
    const float* y      = (const float*)d_in[1];
    const float* data   = (const float*)d_in[2];
    float* out = (float*)d_out;

    nl_main<<<BATCH, ELEMS>>>(y_pred, y, data, out);
}

// round 10
// speedup vs baseline: 2.0299x; 1.0410x over previous
#include <cuda_runtime.h>

// NutritionLoss: Gaussian soft-lookup over NF=1000 foods is numerically a
// one-hot for integer ids (off-weight exp(-100) ~ 3.7e-44) -> hard gather.
//
//   loss = 5 * mean_b sum_c | sum_{d,m,s} (data[pid,c]*pamt - data[tid,c]*tamt) / 700 |
//
// R7 -> R8: latency-chain excision. Kernel is idle-clock latency-bound
// (all pipes <2%). Per-block fabs(batch sum) atomicAdds straight into a
// global accumulator (abs is per-batch = per-block, so this is exact math),
// last block atomicExch-reads-and-resets it. Category combine moved into
// warp-0 shuffles -> one syncthreads total, no smem roundtrip #2, no
// s_last broadcast, no 64-load serial fold in the last block.

#define NF 1000
#define NC 5
#define ELEMS 448   // D*M*S = 7*4*16
#define BATCH 64
#define NWARPS 14   // 448 / 32

__device__ float d_gsum = 0.0f;        // self-resetting via atomicExch in last block
__device__ unsigned int d_count = 0;   // atomicInc(.,BATCH-1) wraps -> self-resets

__global__ __launch_bounds__(ELEMS) void nl_main(
    const float* __restrict__ y_pred,   // [B,D,M,S,2] interleaved (id, amt)
    const float* __restrict__ y,        // [B,D,M,S,2]
    const float* __restrict__ data,     // [NF,NC]
    float* __restrict__ out)            // scalar
{
    __shared__ float swarp[NWARPS][NC];

    const int t = threadIdx.x;
    const int b = blockIdx.x;

    // One (d,m,s) slot per thread; (id, amt) pairs interleaved -> float2.
    const float2 yp = reinterpret_cast<const float2*>(y_pred)[b * ELEMS + t];
    const float2 yt = reinterpret_cast<const float2*>(y)[b * ELEMS + t];

    const int pid = __float2int_rn(yp.x);   // matches jnp.round (no .5 cases)
    const int tid = __float2int_rn(yt.x);   // true ids are exact integers
    const float pamt = yp.y;
    const float tamt = yt.y;

    // Direct gather from the 20KB table (L2-resident); 10 independent LDGs.
    float acc[NC];
    #pragma unroll
    for (int c = 0; c < NC; c++)
        acc[c] = __ldg(&data[pid * NC + c]) * pamt
               - __ldg(&data[tid * NC + c]) * tamt;

    // Warp-level tree reduction of the 5 signed category sums.
    const unsigned full = 0xffffffffu;   // 448 = 14 full warps
    #pragma unroll
    for (int c = 0; c < NC; c++) {
        float v = acc[c];
        #pragma unroll
        for (int o = 16; o > 0; o >>= 1) v += __shfl_down_sync(full, v, o);
        if ((t & 31) == 0) swarp[t >> 5][c] = v;
    }
    __syncthreads();

    // Threads 0..7 (warp 0 lanes 0..7): lane c<5 sums category c over the
    // 14 warps and takes |.|; lanes 5..7 carry 0. Then a 3-level shuffle
    // folds lanes 0..7 into lane 0. No second syncthreads needed.
    if (t < 8) {
        float v = 0.0f;
        if (t < NC) {
            float s = 0.0f;
            #pragma unroll
            for (int w = 0; w < NWARPS; w++) s += swarp[w][t];
            v = fabsf(s);
        }
        const unsigned m8 = 0xffu;
        v += __shfl_down_sync(m8, v, 4);
        v += __shfl_down_sync(m8, v, 2);
        v += __shfl_down_sync(m8, v, 1);

        if (t == 0) {
            atomicAdd(&d_gsum, v);          // per-batch |sum| -> global accumulator
            __threadfence();                // release: gsum add before count inc
            unsigned prev = atomicInc(&d_count, BATCH - 1);  // wraps -> self-reset
            if (prev == BATCH - 1) {
                __threadfence();            // acquire: see all gsum adds
                float total = atomicExch(&d_gsum, 0.0f);     // read + reset in one
                // * (1/700) elementwise, * (1/B) batch mean, * 5 penalty
                out[0] = total * (5.0f / (700.0f * (float)BATCH));
            }
        }
    }
}

extern "C" void kernel_launch(void* const* d_in, const int* in_sizes, int n_in,
                              void* d_out, int out_size) {
    const float* y_pred = (const float*)d_in[0];
    const float* y      = (const float*)d_in[1];
    const float* data   = (const float*)d_in[2];
    float* out = (float*)d_out;

    nl_main<<<BATCH, ELEMS>>>(y_pred, y, data, out);
}

// round 12
// speedup vs baseline: 2.2954x; 1.1308x over previous
#include <cuda_runtime.h>

// NutritionLoss: Gaussian soft-lookup over NF=1000 foods is numerically a
// one-hot for integer ids (off-weight exp(-100) ~ 3.7e-44) -> hard gather.
//
//   loss = 5 * mean_b sum_c | sum_{d,m,s} (data[pid,c]*pamt - data[tid,c]*tamt) / 700 |
//
// R10 -> R11: single-atomic packed tail. Kernel is latency-bound at
// near-idle clocks (~3ns/cyc), so the old tail (ATOMG + membar.gl + ATOMG
// + membar.gl + ATOMG) was ~1000 cycles of the ~2300-cycle critical path.
// Now: per-batch |sum| as 2^22 fixed point + arrival counter at bit 56,
// ONE atomicAdd(ull). Same word carries data and flag -> zero fences.
// Last block derives the exact total from prev+payload (no re-read),
// resets with one atomicExch for graph-replay determinism.

#define NF 1000
#define NC 5
#define ELEMS 448   // D*M*S = 7*4*16
#define BATCH 64
#define NWARPS 14   // 448 / 32

#define FP_SCALE 4194304.0f            // 2^22
#define CNT_ONE  (1ULL << 56)
#define SUM_MASK (CNT_ONE - 1ULL)

__device__ unsigned long long d_acc = 0ULL;  // [63:56]=arrival count, [55:0]=fixed-point sum

__global__ __launch_bounds__(ELEMS) void nl_main(
    const float* __restrict__ y_pred,   // [B,D,M,S,2] interleaved (id, amt)
    const float* __restrict__ y,        // [B,D,M,S,2]
    const float* __restrict__ data,     // [NF,NC]
    float* __restrict__ out)            // scalar
{
    __shared__ float swarp[NWARPS][NC];

    const int t = threadIdx.x;
    const int b = blockIdx.x;

    // One (d,m,s) slot per thread; (id, amt) pairs interleaved -> float2.
    const float2 yp = reinterpret_cast<const float2*>(y_pred)[b * ELEMS + t];
    const float2 yt = reinterpret_cast<const float2*>(y)[b * ELEMS + t];

    const int pid = __float2int_rn(yp.x);   // matches jnp.round (no .5 cases)
    const int tid = __float2int_rn(yt.x);   // true ids are exact integers
    const float pamt = yp.y;
    const float tamt = yt.y;

    // Direct gather from the 20KB table (L2-resident); 10 independent LDGs.
    float acc[NC];
    #pragma unroll
    for (int c = 0; c < NC; c++)
        acc[c] = __ldg(&data[pid * NC + c]) * pamt
               - __ldg(&data[tid * NC + c]) * tamt;

    // Warp-level tree reduction of the 5 signed category sums.
    const unsigned full = 0xffffffffu;   // 448 = 14 full warps
    #pragma unroll
    for (int c = 0; c < NC; c++) {
        float v = acc[c];
        #pragma unroll
        for (int o = 16; o > 0; o >>= 1) v += __shfl_down_sync(full, v, o);
        if ((t & 31) == 0) swarp[t >> 5][c] = v;
    }
    __syncthreads();

    // Warp-0 lanes 0..7: lane c<5 sums category c over 14 warps, |.|;
    // lanes 5..7 carry 0. 3-level shuffle folds into lane 0.
    if (t < 8) {
        float v = 0.0f;
        if (t < NC) {
            float s = 0.0f;
            #pragma unroll
            for (int w = 0; w < NWARPS; w++) s += swarp[w][t];
            v = fabsf(s);
        }
        const unsigned m8 = 0xffu;
        v += __shfl_down_sync(m8, v, 4);
        v += __shfl_down_sync(m8, v, 2);
        v += __shfl_down_sync(m8, v, 1);

        if (t == 0) {
            // Pack: fixed-point per-batch |sum| + arrival tick. One atomic,
            // no fences: the word is its own synchronization.
            unsigned long long payload =
                (unsigned long long)__float2ull_rn(v * FP_SCALE) | CNT_ONE;
            unsigned long long prev = atomicAdd(&d_acc, payload);
            if ((prev >> 56) == (BATCH - 1)) {
                unsigned long long total_fx = (prev + payload) & SUM_MASK;
                atomicExch(&d_acc, 0ULL);     // self-reset for next graph replay
                float total = (float)total_fx * (1.0f / FP_SCALE);
                // * (1/700) elementwise, * (1/B) batch mean, * 5 penalty
                out[0] = total * (5.0f / (700.0f * (float)BATCH));
            }
        }
    }
}

extern "C" void kernel_launch(void* const* d_in, const int* in_sizes, int n_in,
                              void* d_out, int out_size) {
    const float* y_pred = (const float*)d_in[0];
    const float* y      = (const float*)d_in[1];
    const float* data   = (const float*)d_in[2];
    float* out = (float*)d_out;

    nl_main<<<BATCH, ELEMS>>>(y_pred, y, data, out);
}